// round 1
// baseline (speedup 1.0000x reference)
#include <cuda_runtime.h>

// DynamicGraphModule_15144054686343
//
// Reference math reduces analytically:
//   scores[i,j] = row_term[i] + col_term[j] + b   (rank-1 + const)
//   adj = where(corr > 1.5, corr, 0)  -> elements in {0} U (1.5, inf)
//   adj = where(adj < -1.5, adj, 0)   -> identically ZERO
//   out = adj @ (e @ W_gcn) + b_gcn   == broadcast(b_gcn) exactly (fp32: 0*x sums to 0.0)
//
// So the kernel is a broadcast of b_gcn [512] into out [1, 4096, 512].
// Memory-bound: one 8 MB store. Vectorized float4 stores, b_gcn served from L1/L2.

static constexpr int D_OUT = 512;           // OUT_GCN
static constexpr int D_OUT_VEC4 = D_OUT / 4; // 128 float4 per row

__global__ void __launch_bounds__(256)
broadcast_bias_kernel(const float4* __restrict__ bias4,
                      float4* __restrict__ out4,
                      int n_vec4)
{
    int idx = blockIdx.x * blockDim.x + threadIdx.x;
    if (idx < n_vec4) {
        // column within a row, as float4 index (row length 512 floats = 128 float4)
        out4[idx] = bias4[idx & (D_OUT_VEC4 - 1)];
    }
}

extern "C" void kernel_launch(void* const* d_in, const int* in_sizes, int n_in,
                              void* d_out, int out_size)
{
    // metadata order:
    // 0 spans_embeddings, 1 W_c1, 2 b_c1, 3 W_c2, 4 b_c2,
    // 5 W_link, 6 b_link, 7 W_gcn, 8 b_gcn
    const float4* bias4 = (const float4*)d_in[8];
    float4* out4 = (float4*)d_out;

    int n_vec4 = out_size / 4;              // out_size = 1*4096*512, divisible by 4
    int threads = 256;
    int blocks = (n_vec4 + threads - 1) / threads;
    broadcast_bias_kernel<<<blocks, threads>>>(bias4, out4, n_vec4);
}